// round 1
// baseline (speedup 1.0000x reference)
#include <cuda_runtime.h>
#include <cstdint>

// ----------------------------------------------------------------------------
// BaseLUTLayer: out[b,o] = sum_k lut[o,k] * prod_j ( bit_j(k)*x_j + (1-bit_j(k))*(1-x_j) )
// with x_j = x[b, mapping[o,j]],  N_BITS=6, N_ENTRIES=64.
//
// Algorithm: multilinear fold (lerp tree) over the 64-entry LUT:
//   t5[k] = (1-x5)*lut[k] + x5*lut[k+32]   (32 lerps)
//   t4[k] = (1-x4)*t5[k]  + x4*t5[k+16]    (16 lerps)  ... down to scalar.
// Entries are packed in (even,odd) f32x2 pairs (pairing on bit 0), so the 5
// upper folds run on packed fma.rn.f32x2 / mul.rn.f32x2 (sm_100+ packed fp32),
// halving fma-pipe instruction count. Final bit-0 lerp is scalar.
//
// Memory: x is pre-transposed (xT[IN][B]) so warp lanes (b-axis) load x
// coalesced. LUT tile lives in smem (warp-broadcast LDS.64). Results are
// staged in smem and written with o-fastest threads for full-sector stores.
// ----------------------------------------------------------------------------

#define B_TILE 32
#define O_TILE 8

// scratch for transposed x (allocation-free rule: __device__ global)
__device__ float g_xT[4 * 1024 * 1024];

static __device__ __forceinline__ unsigned long long bcast2(float v) {
    unsigned long long r;
    asm("mov.b64 %0, {%1, %2};" : "=l"(r) : "f"(v), "f"(v));
    return r;
}
static __device__ __forceinline__ unsigned long long mul2(unsigned long long a, unsigned long long b) {
    unsigned long long d;
    asm("mul.rn.f32x2 %0, %1, %2;" : "=l"(d) : "l"(a), "l"(b));
    return d;
}
static __device__ __forceinline__ unsigned long long fma2(unsigned long long a, unsigned long long b, unsigned long long c) {
    unsigned long long d;
    asm("fma.rn.f32x2 %0, %1, %2, %3;" : "=l"(d) : "l"(a), "l"(b), "l"(c));
    return d;
}

__global__ void transpose_kernel(const float* __restrict__ x, float* __restrict__ xT,
                                 int B, int IN) {
    __shared__ float tile[32][33];
    int c  = blockIdx.x * 32 + threadIdx.x;   // IN index
    int r0 = blockIdx.y * 32;                 // B base
#pragma unroll
    for (int i = 0; i < 32; i += 8) {
        int r = r0 + threadIdx.y + i;
        if (r < B && c < IN)
            tile[threadIdx.y + i][threadIdx.x] = x[(size_t)r * IN + c];
    }
    __syncthreads();
    int b2  = r0 + threadIdx.x;               // B index (now contiguous)
    int in0 = blockIdx.x * 32;                // IN base
#pragma unroll
    for (int i = 0; i < 32; i += 8) {
        int r = in0 + threadIdx.y + i;
        if (r < IN && b2 < B)
            xT[(size_t)r * B + b2] = tile[threadIdx.x][threadIdx.y + i];
    }
}

__global__ __launch_bounds__(B_TILE * O_TILE)
void lut_fold_kernel(const float* __restrict__ xT,
                     const float* __restrict__ lut_table,
                     const int*   __restrict__ mapping,
                     float* __restrict__ out,
                     int B, int OUT) {
    __shared__ unsigned long long s_lut[O_TILE][32];   // 32 f32x2 pairs per output
    __shared__ int                s_map[O_TILE][6];
    __shared__ float              s_res[O_TILE][B_TILE + 1];

    const int tx  = threadIdx.x;           // b lane
    const int ty  = threadIdx.y;           // o within tile
    const int tid = ty * B_TILE + tx;
    const int b0  = blockIdx.x * B_TILE;
    const int o0  = blockIdx.y * O_TILE;

    // cooperative tile loads
    const unsigned long long* lut64 = reinterpret_cast<const unsigned long long*>(lut_table);
    for (int i = tid; i < O_TILE * 32; i += B_TILE * O_TILE) {
        int oo = i >> 5, p = i & 31;
        int o  = o0 + oo;
        if (o < OUT) s_lut[oo][p] = lut64[(size_t)o * 32 + p];
    }
    if (tid < O_TILE * 6) {
        int oo = tid / 6, j = tid % 6;
        int o = o0 + oo;
        s_map[oo][j] = (o < OUT) ? mapping[(size_t)o * 6 + j] : 0;
    }
    __syncthreads();

    const int b = b0 + tx;
    const bool valid_b = (b < B);

    float xv[6];
#pragma unroll
    for (int j = 0; j < 6; j++) {
        xv[j] = valid_b ? __ldg(&xT[(size_t)s_map[ty][j] * B + b]) : 0.5f;
    }

    unsigned long long X[5], OX[5];
#pragma unroll
    for (int j = 1; j < 6; j++) {
        X[j - 1]  = bcast2(xv[j]);
        OX[j - 1] = bcast2(1.0f - xv[j]);
    }

    unsigned long long t[16];
#pragma unroll
    for (int k = 0; k < 16; k++)   // fold bit 5: pair p vs p+16
        t[k] = fma2(X[4], s_lut[ty][k + 16], mul2(OX[4], s_lut[ty][k]));
#pragma unroll
    for (int k = 0; k < 8; k++)    // fold bit 4
        t[k] = fma2(X[3], t[k + 8], mul2(OX[3], t[k]));
#pragma unroll
    for (int k = 0; k < 4; k++)    // fold bit 3
        t[k] = fma2(X[2], t[k + 4], mul2(OX[2], t[k]));
#pragma unroll
    for (int k = 0; k < 2; k++)    // fold bit 2
        t[k] = fma2(X[1], t[k + 2], mul2(OX[1], t[k]));
    t[0] = fma2(X[0], t[1], mul2(OX[0], t[0]));   // fold bit 1

    float lo, hi;
    asm("mov.b64 {%0, %1}, %2;" : "=f"(lo), "=f"(hi) : "l"(t[0]));
    float res = fmaf(xv[0], hi, (1.0f - xv[0]) * lo);   // fold bit 0

    s_res[ty][tx] = res;
    __syncthreads();

    // sector-friendly store: o runs fastest across consecutive threads
    int oo = tid & (O_TILE - 1);
    int bb = tid >> 3;   // log2(O_TILE)
    int o  = o0 + oo;
    int bw = b0 + bb;
    if (bw < B && o < OUT)
        out[(size_t)bw * OUT + o] = s_res[oo][bb];
}

extern "C" void kernel_launch(void* const* d_in, const int* in_sizes, int n_in,
                              void* d_out, int out_size) {
    const float* x       = (const float*)d_in[0];
    const float* lut     = (const float*)d_in[1];
    const int*   mapping = (const int*)d_in[2];
    float*       out     = (float*)d_out;

    int OUT = in_sizes[2] / 6;          // mapping is (OUT, 6)
    int B   = out_size / OUT;           // out is (B, OUT)
    int IN  = in_sizes[0] / B;          // x is (B, IN)

    float* xT = nullptr;
    cudaGetSymbolAddress((void**)&xT, g_xT);

    dim3 tb(32, 8);
    dim3 tg((IN + 31) / 32, (B + 31) / 32);
    transpose_kernel<<<tg, tb>>>(x, xT, B, IN);

    dim3 blk(B_TILE, O_TILE);
    dim3 grd((B + B_TILE - 1) / B_TILE, (OUT + O_TILE - 1) / O_TILE);
    lut_fold_kernel<<<grd, blk>>>(xT, lut, mapping, out, B, OUT);
}

// round 2
// speedup vs baseline: 1.2911x; 1.2911x over previous
#include <cuda_runtime.h>
#include <cstdint>

// ----------------------------------------------------------------------------
// BaseLUTLayer via multilinear fold, f32x2-packed over the BATCH axis.
//
// out[b,o] = fold over 6 bits of lut[o][0..63] with weights x_j = x[b, map[o,j]].
// Lerp-diff form: lerp(lo,hi,x) = fma(x, hi-lo, lo)  (2 fma-pipe ops, packed).
//
// Packing: each thread computes TWO adjacent b's; the f32x2 lanes are (b, b+1),
// so X[j] comes packed straight from an 8-byte load of the transposed x
// (xT[in][b]) -- no scalar->vector broadcast MOVs.
// LUT values are warp-uniform: a block prologue duplicates each entry {L,L}
// and precomputes the bit-5 difference {D,D}=lut[k+32]-lut[k], stored
// interleaved as ulonglong2 so one LDS.128 feeds one fused level-5 fma2.
// ----------------------------------------------------------------------------

#define O_TILE 8            // outputs per block, one per warp
#define BPT    2            // batch elements per thread
#define B_TILE (32 * BPT)   // 64

__device__ float g_xT[4 * 1024 * 1024];   // transposed x scratch (no allocs allowed)

static __device__ __forceinline__ unsigned long long pack2(float lo, float hi) {
    unsigned long long r;
    asm("mov.b64 %0, {%1, %2};" : "=l"(r) : "f"(lo), "f"(hi));
    return r;
}
static __device__ __forceinline__ void unpack2(unsigned long long v, float& lo, float& hi) {
    asm("mov.b64 {%0, %1}, %2;" : "=f"(lo), "=f"(hi) : "l"(v));
}
static __device__ __forceinline__ unsigned long long fma2(unsigned long long a,
                                                          unsigned long long b,
                                                          unsigned long long c) {
    unsigned long long d;
    asm("fma.rn.f32x2 %0, %1, %2, %3;" : "=l"(d) : "l"(a), "l"(b), "l"(c));
    return d;
}
// packed lerp: v + x*(w - v)   (two fma2, no extra setup)
static __device__ __forceinline__ unsigned long long lerp2(unsigned long long v,
                                                           unsigned long long w,
                                                           unsigned long long x,
                                                           unsigned long long NEG1) {
    unsigned long long d = fma2(v, NEG1, w);   // w - v
    return fma2(x, d, v);
}

__global__ void transpose_kernel(const float* __restrict__ x, float* __restrict__ xT,
                                 int B, int IN) {
    __shared__ float tile[32][33];
    int c  = blockIdx.x * 32 + threadIdx.x;
    int r0 = blockIdx.y * 32;
#pragma unroll
    for (int i = 0; i < 32; i += 8) {
        int r = r0 + threadIdx.y + i;
        if (r < B && c < IN)
            tile[threadIdx.y + i][threadIdx.x] = x[(size_t)r * IN + c];
    }
    __syncthreads();
    int b2  = r0 + threadIdx.x;
    int in0 = blockIdx.x * 32;
#pragma unroll
    for (int i = 0; i < 32; i += 8) {
        int r = in0 + threadIdx.y + i;
        if (r < IN && b2 < B)
            xT[(size_t)r * B + b2] = tile[threadIdx.x][threadIdx.y + i];
    }
}

__global__ __launch_bounds__(32 * O_TILE)
void lut_fold_kernel(const float* __restrict__ xT,
                     const float* __restrict__ lut_table,
                     const int*   __restrict__ mapping,
                     float* __restrict__ out,
                     int B, int OUT) {
    // interleaved per-entry {Ldup, Ddup}: 8 o * 32 entries * 16B = 4 KB
    __shared__ ulonglong2 s_lut[O_TILE][32];
    __shared__ int        s_map[O_TILE][6];
    __shared__ float      s_res[B_TILE][O_TILE + 2];   // +2 pad: 40B rows, 8B aligned

    const int lane = threadIdx.x;
    const int ty   = threadIdx.y;                      // o within tile / warp id
    const int tid  = ty * 32 + lane;
    const int b0   = blockIdx.x * B_TILE;
    const int o0   = blockIdx.y * O_TILE;

    // ---- prologue: build duplicated LUT + bit-5 diffs, stage mapping ----
    {
        int oo = tid >> 5, k = tid & 31;               // 256 threads -> 8x32 entries
        int o = o0 + oo;
        float lo = 0.f, hi = 0.f;
        if (o < OUT) {
            lo = __ldg(&lut_table[(size_t)o * 64 + k]);
            hi = __ldg(&lut_table[(size_t)o * 64 + k + 32]);
        }
        ulonglong2 e;
        e.x = pack2(lo, lo);
        e.y = pack2(hi - lo, hi - lo);
        s_lut[oo][k] = e;
    }
    if (tid < O_TILE * 6) {
        int oo = tid / 6, j = tid % 6;
        int o = o0 + oo;
        s_map[oo][j] = (o < OUT) ? mapping[(size_t)o * 6 + j] : 0;
    }
    __syncthreads();

    const unsigned long long NEG1 = pack2(-1.0f, -1.0f);

    const int b = b0 + 2 * lane;                       // this thread's batch pair
    const bool vb = (b + 1 < B);

    // ---- packed x loads: lanes are (b, b+1), straight from memory ----
    unsigned long long X[6];
#pragma unroll
    for (int j = 0; j < 6; j++) {
        int m = s_map[ty][j];
        X[j] = vb ? *reinterpret_cast<const unsigned long long*>(&xT[(size_t)m * B + b])
                  : 0ull;
    }

    const ulonglong2* lrow = &s_lut[ty][0];

    // ---- fold: bit5 fused at load (precomputed diff), then bits 2,1,0 within
    //      each (b4,b3) group of 8 entries, then bits 3 and 4 across groups ----
    unsigned long long r[4];
#pragma unroll
    for (int g = 0; g < 4; g++) {
        unsigned long long v[8];
#pragma unroll
        for (int i = 0; i < 8; i++) {
            ulonglong2 e = lrow[g * 8 + i];            // LDS.128, warp-broadcast
            v[i] = fma2(X[5], e.y, e.x);               // L + x5*D
        }
        unsigned long long w[4];
#pragma unroll
        for (int i = 0; i < 4; i++) w[i] = lerp2(v[i], v[i + 4], X[2], NEG1);
        unsigned long long u0 = lerp2(w[0], w[2], X[1], NEG1);
        unsigned long long u1 = lerp2(w[1], w[3], X[1], NEG1);
        r[g] = lerp2(u0, u1, X[0], NEG1);
    }
    unsigned long long s0  = lerp2(r[0], r[1], X[3], NEG1);
    unsigned long long s1  = lerp2(r[2], r[3], X[3], NEG1);
    unsigned long long res = lerp2(s0, s1, X[4], NEG1);

    // ---- stage + sector-friendly writeout (o fastest, float2 stores) ----
    float rlo, rhi;
    unpack2(res, rlo, rhi);
    s_res[2 * lane + 0][ty] = rlo;
    s_res[2 * lane + 1][ty] = rhi;
    __syncthreads();

    int oo2 = tid & 3;            // o-pair index: covers o0 + 2*oo2, +1
    int bb  = tid >> 2;           // 0..63
    int o   = o0 + oo2 * 2;
    int bw  = b0 + bb;
    if (bw < B && o + 1 < OUT) {
        float2 val = *reinterpret_cast<float2*>(&s_res[bb][oo2 * 2]);
        *reinterpret_cast<float2*>(&out[(size_t)bw * OUT + o]) = val;
    }
}

extern "C" void kernel_launch(void* const* d_in, const int* in_sizes, int n_in,
                              void* d_out, int out_size) {
    const float* x       = (const float*)d_in[0];
    const float* lut     = (const float*)d_in[1];
    const int*   mapping = (const int*)d_in[2];
    float*       out     = (float*)d_out;

    int OUT = in_sizes[2] / 6;          // mapping is (OUT, 6)
    int B   = out_size / OUT;           // out is (B, OUT)
    int IN  = in_sizes[0] / B;          // x is (B, IN)

    float* xT = nullptr;
    cudaGetSymbolAddress((void**)&xT, g_xT);

    dim3 tb(32, 8);
    dim3 tg((IN + 31) / 32, (B + 31) / 32);
    transpose_kernel<<<tg, tb>>>(x, xT, B, IN);

    dim3 blk(32, O_TILE);
    dim3 grd((B + B_TILE - 1) / B_TILE, (OUT + O_TILE - 1) / O_TILE);
    lut_fold_kernel<<<grd, blk>>>(xT, lut, mapping, out, B, OUT);
}

// round 3
// speedup vs baseline: 1.3333x; 1.0327x over previous
#include <cuda_runtime.h>
#include <cstdint>

// ----------------------------------------------------------------------------
// BaseLUTLayer, multilinear COEFFICIENT basis + f32x2 batch packing.
//
// Stage 1: transpose x -> xT[IN][B] (coalesced batch-axis loads later).
// Stage 2: Moebius transform lut[o][64] -> multilinear coefficients C[o][64]
//          (per bit j: a[k] -= a[k ^ (1<<j)] for k with bit j set). Then
//          out = nested Horner: v = c_even + x_j * c_odd per bit  -> 63 fma.
// Stage 3: fold kernel. Each thread: 4 batch elems (two f32x2 pairs) x 1 out.
//          Coefficients duplicated {c,c} in smem; one LDS.128 = one coeff pair
//          feeding two fma2 (bit-0 level). 63 fma2 per b-pair, no mul/sub.
// ----------------------------------------------------------------------------

#define O_TILE 8
#define BPT    4
#define B_TILE (32 * BPT)   // 128

__device__ float g_xT[4 * 1024 * 1024];   // transposed x scratch
__device__ float g_C [1 * 1024 * 1024];   // coefficient table scratch

static __device__ __forceinline__ unsigned long long pack2(float lo, float hi) {
    unsigned long long r;
    asm("mov.b64 %0, {%1, %2};" : "=l"(r) : "f"(lo), "f"(hi));
    return r;
}
static __device__ __forceinline__ void unpack2(unsigned long long v, float& lo, float& hi) {
    asm("mov.b64 {%0, %1}, %2;" : "=f"(lo), "=f"(hi) : "l"(v));
}
static __device__ __forceinline__ unsigned long long fma2(unsigned long long a,
                                                          unsigned long long b,
                                                          unsigned long long c) {
    unsigned long long d;
    asm("fma.rn.f32x2 %0, %1, %2, %3;" : "=l"(d) : "l"(a), "l"(b), "l"(c));
    return d;
}

__global__ void transpose_kernel(const float* __restrict__ x, float* __restrict__ xT,
                                 int B, int IN) {
    __shared__ float tile[32][33];
    int c  = blockIdx.x * 32 + threadIdx.x;
    int r0 = blockIdx.y * 32;
#pragma unroll
    for (int i = 0; i < 32; i += 8) {
        int r = r0 + threadIdx.y + i;
        if (r < B && c < IN)
            tile[threadIdx.y + i][threadIdx.x] = x[(size_t)r * IN + c];
    }
    __syncthreads();
    int b2  = r0 + threadIdx.x;
    int in0 = blockIdx.x * 32;
#pragma unroll
    for (int i = 0; i < 32; i += 8) {
        int r = in0 + threadIdx.y + i;
        if (r < IN && b2 < B)
            xT[(size_t)r * B + b2] = tile[threadIdx.x][threadIdx.y + i];
    }
}

// Moebius (finite-difference) transform: one thread per output row.
__global__ void coeff_kernel(const float* __restrict__ lut, float* __restrict__ C, int OUT) {
    int o = blockIdx.x * blockDim.x + threadIdx.x;
    if (o >= OUT) return;
    float a[64];
    const float4* src = reinterpret_cast<const float4*>(lut + (size_t)o * 64);
#pragma unroll
    for (int i = 0; i < 16; i++) {
        float4 v = __ldg(&src[i]);
        a[4 * i] = v.x; a[4 * i + 1] = v.y; a[4 * i + 2] = v.z; a[4 * i + 3] = v.w;
    }
#pragma unroll
    for (int j = 0; j < 6; j++) {
        int s = 1 << j;
#pragma unroll
        for (int k = 0; k < 64; k++)
            if (k & s) a[k] -= a[k ^ s];
    }
    float4* dst = reinterpret_cast<float4*>(C + (size_t)o * 64);
#pragma unroll
    for (int i = 0; i < 16; i++)
        dst[i] = make_float4(a[4 * i], a[4 * i + 1], a[4 * i + 2], a[4 * i + 3]);
}

__global__ __launch_bounds__(32 * O_TILE)
void lut_fold_kernel(const float* __restrict__ xT,
                     const float* __restrict__ C,
                     const int*   __restrict__ mapping,
                     float* __restrict__ out,
                     int B, int OUT) {
    __shared__ ulonglong2 s_lut[O_TILE][32];          // {dup c_even, dup c_odd} pairs
    __shared__ int        s_map[O_TILE][6];
    __shared__ float      s_res[O_TILE][B_TILE + 4];  // row = 132 floats, 16B aligned

    const int lane = threadIdx.x;
    const int ty   = threadIdx.y;
    const int tid  = ty * 32 + lane;
    const int b0   = blockIdx.x * B_TILE;
    const int o0   = blockIdx.y * O_TILE;

    // prologue: duplicated coefficient pairs into smem
    {
        int oo = tid >> 5, k = tid & 31;
        int o  = o0 + oo;
        float2 c = make_float2(0.f, 0.f);
        if (o < OUT) c = *reinterpret_cast<const float2*>(&C[(size_t)o * 64 + 2 * k]);
        ulonglong2 e;
        e.x = pack2(c.x, c.x);
        e.y = pack2(c.y, c.y);
        s_lut[oo][k] = e;
    }
    if (tid < O_TILE * 6) {
        int oo = tid / 6, j = tid % 6;
        int o = o0 + oo;
        s_map[oo][j] = (o < OUT) ? mapping[(size_t)o * 6 + j] : 0;
    }
    __syncthreads();

    const int bq = b0 + lane * 4;                     // 4 consecutive b per thread
    const bool vb = (bq + 3 < B);

    // packed x loads: one LDG.128 per bit = both f32x2 sets
    unsigned long long Xa[6], Xb[6];
#pragma unroll
    for (int j = 0; j < 6; j++) {
        if (vb) {
            ulonglong2 xv = *reinterpret_cast<const ulonglong2*>(&xT[(size_t)s_map[ty][j] * B + bq]);
            Xa[j] = xv.x;
            Xb[j] = xv.y;
        } else {
            Xa[j] = 0ull; Xb[j] = 0ull;
        }
    }

    const ulonglong2* lrow = &s_lut[ty][0];

    unsigned long long ra[4], rb[4];
#pragma unroll
    for (int g = 0; g < 4; g++) {
        unsigned long long va[8], vbv[8];
#pragma unroll
        for (int i = 0; i < 8; i++) {
            ulonglong2 e = lrow[g * 8 + i];           // LDS.128 warp-broadcast
            va[i]  = fma2(Xa[0], e.y, e.x);           // bit 0
            vbv[i] = fma2(Xb[0], e.y, e.x);
        }
#pragma unroll
        for (int i = 0; i < 4; i++) {                 // bit 1
            va[i]  = fma2(Xa[1], va[2 * i + 1],  va[2 * i]);
            vbv[i] = fma2(Xb[1], vbv[2 * i + 1], vbv[2 * i]);
        }
#pragma unroll
        for (int i = 0; i < 2; i++) {                 // bit 2
            va[i]  = fma2(Xa[2], va[2 * i + 1],  va[2 * i]);
            vbv[i] = fma2(Xb[2], vbv[2 * i + 1], vbv[2 * i]);
        }
        ra[g] = fma2(Xa[3], va[1],  va[0]);           // bit 3
        rb[g] = fma2(Xb[3], vbv[1], vbv[0]);
    }
    unsigned long long sa0 = fma2(Xa[4], ra[1], ra[0]);   // bit 4
    unsigned long long sa1 = fma2(Xa[4], ra[3], ra[2]);
    unsigned long long sb0 = fma2(Xb[4], rb[1], rb[0]);
    unsigned long long sb1 = fma2(Xb[4], rb[3], rb[2]);
    unsigned long long resa = fma2(Xa[5], sa1, sa0);      // bit 5
    unsigned long long resb = fma2(Xb[5], sb1, sb0);

    // stage: s_res[o_local][b_local], STS.128 conflict-free
    float r0, r1, r2, r3;
    unpack2(resa, r0, r1);
    unpack2(resb, r2, r3);
    *reinterpret_cast<float4*>(&s_res[ty][lane * 4]) = make_float4(r0, r1, r2, r3);
    __syncthreads();

    // writeout: o fastest, float4 stores (full 32B sectors)
    int bw   = tid >> 1;
    int half = tid & 1;
    int o    = o0 + half * 4;
    int bg   = b0 + bw;
    if (bg < B && o + 3 < OUT) {
        float4 val = make_float4(s_res[half * 4 + 0][bw],
                                 s_res[half * 4 + 1][bw],
                                 s_res[half * 4 + 2][bw],
                                 s_res[half * 4 + 3][bw]);
        *reinterpret_cast<float4*>(&out[(size_t)bg * OUT + o]) = val;
    }
}

extern "C" void kernel_launch(void* const* d_in, const int* in_sizes, int n_in,
                              void* d_out, int out_size) {
    const float* x       = (const float*)d_in[0];
    const float* lut     = (const float*)d_in[1];
    const int*   mapping = (const int*)d_in[2];
    float*       out     = (float*)d_out;

    int OUT = in_sizes[2] / 6;          // mapping is (OUT, 6)
    int B   = out_size / OUT;           // out is (B, OUT)
    int IN  = in_sizes[0] / B;          // x is (B, IN)

    float* xT = nullptr;
    float* C  = nullptr;
    cudaGetSymbolAddress((void**)&xT, g_xT);
    cudaGetSymbolAddress((void**)&C,  g_C);

    dim3 tb(32, 8);
    dim3 tg((IN + 31) / 32, (B + 31) / 32);
    transpose_kernel<<<tg, tb>>>(x, xT, B, IN);

    coeff_kernel<<<(OUT + 63) / 64, 64>>>(lut, C, OUT);

    dim3 blk(32, O_TILE);
    dim3 grd((B + B_TILE - 1) / B_TILE, (OUT + O_TILE - 1) / O_TILE);
    lut_fold_kernel<<<grd, blk>>>(xT, C, mapping, out, B, OUT);
}